// round 1
// baseline (speedup 1.0000x reference)
#include <cuda_runtime.h>
#include <math.h>

#define N 256
#define LINES 8
#define LSTR 257          // padded line stride (float2 units) to break bank conflicts
#define NTILE 128         // 32 batch * 4 probe modes
#define BATCH 32

// 64 MB scratch for psi in row-transformed domain: [tile][y][kx]
__device__ float2 g_psi[NTILE * N * N];
// transposed transfer function: g_Ht[kx*256 + ky] = H[ky][kx]
__device__ float2 g_Ht[N * N];

__device__ __forceinline__ float2 cmulf(float2 a, float2 b) {
    return make_float2(a.x * b.x - a.y * b.y, a.x * b.y + a.y * b.x);
}

__device__ __forceinline__ void fill_tw(float2* sT, int t) {
    if (t < 128) {
        float s, c;
        sincospif((float)t / 128.0f, &s, &c);   // angle = 2*pi*t/256
        sT[t] = make_float2(c, -s);             // forward twiddle e^{-i*2pi t/256}
    }
}

// Stockham radix-2 FFT over 8 lines of 256 points each. 256 threads.
// Data starts in sA (stride LSTR per line), ends in sA (8 stages = even swaps).
// Caller must __syncthreads() before calling. Ends with a __syncthreads().
template<bool INV>
__device__ __forceinline__ void fft_lines(float2* sA, float2* sB,
                                          const float2* sT, int t) {
    float2* src = sA;
    float2* dst = sB;
    const int j  = t & 127;    // butterfly index (fixed per thread)
    const int l0 = t >> 7;     // 0 or 1
    #pragma unroll
    for (int s = 0; s < 8; s++) {
        const int Ns = 1 << s;
        const int jm = j & (Ns - 1);
        float2 w = sT[jm << (7 - s)];
        if (INV) w.y = -w.y;
        const int i0 = ((j >> s) << (s + 1)) + jm;   // expand(j, Ns)
        #pragma unroll
        for (int k = 0; k < 4; k++) {
            const int line = (l0 + 2 * k) * LSTR;
            float2 a = src[line + j];
            float2 b = src[line + j + 128];
            float2 bw = make_float2(b.x * w.x - b.y * w.y,
                                    b.x * w.y + b.y * w.x);
            dst[line + i0]      = make_float2(a.x + bw.x, a.y + bw.y);
            dst[line + i0 + Ns] = make_float2(a.x - bw.x, a.y - bw.y);
        }
        __syncthreads();
        float2* tmp = src; src = dst; dst = tmp;
    }
}

// ---------------------------------------------------------------------------
// Transpose H into g_Ht (tiny, once per launch)
__global__ void k_transpose(const float* __restrict__ Hr,
                            const float* __restrict__ Hi) {
    int i = blockIdx.x * blockDim.x + threadIdx.x;  // 65536 threads
    int ky = i >> 8, kx = i & 255;
    g_Ht[kx * N + ky] = make_float2(Hr[i], Hi[i]);
}

// ---------------------------------------------------------------------------
// Init: psi0 = bilinear_probe * obj_slice0, then forward row FFT -> g_psi
__global__ void k_init_row(const float* __restrict__ obj,    // (1,8,1024,1024,2)
                           const float* __restrict__ probe,  // (4,256,256,2)
                           const float* __restrict__ shifts, // (1024,2)
                           const int*   __restrict__ cpos,   // (1024,2)
                           const int*   __restrict__ idxs) { // (32,)
    __shared__ float2 sA[LINES * LSTR];
    __shared__ float2 sB[LINES * LSTR];
    __shared__ float2 sT[128];
    const int t = threadIdx.x;
    fill_tw(sT, t);

    const int tile = blockIdx.y;
    const int b = tile >> 2, m = tile & 3;
    const int y0 = blockIdx.x * LINES;
    const int idx = idxs[b];
    const int py = cpos[2 * idx], px = cpos[2 * idx + 1];
    const float tH = shifts[2 * idx], tW = shifts[2 * idx + 1];
    const float oyf = floorf(-tH), oxf = floorf(-tW);
    const int oy = (int)oyf, ox = (int)oxf;
    const float wy = -tH - oyf, wx = -tW - oxf;
    const float w00 = (1.f - wy) * (1.f - wx);
    const float w01 = (1.f - wy) * wx;
    const float w10 = wy * (1.f - wx);
    const float w11 = wy * wx;

    const int warp = t >> 5, lane = t & 31;
    const int y = y0 + warp;
    const int yy0 = y + oy;
    const bool v0 = (yy0 >= 0) && (yy0 < N);
    const bool v1 = (yy0 + 1 >= 0) && (yy0 + 1 < N);
    const float2* pr = (const float2*)probe + m * N * N;
    const float2* ob = (const float2*)obj;   // slice 0

    #pragma unroll
    for (int k = 0; k < 8; k++) {
        const int x = lane + 32 * k;
        const int xx0 = x + ox;
        const bool u0 = (xx0 >= 0) && (xx0 < N);
        const bool u1 = (xx0 + 1 >= 0) && (xx0 + 1 < N);
        float2 z = make_float2(0.f, 0.f);
        float2 p00 = (v0 && u0) ? pr[yy0 * N + xx0]           : z;
        float2 p01 = (v0 && u1) ? pr[yy0 * N + xx0 + 1]       : z;
        float2 p10 = (v1 && u0) ? pr[(yy0 + 1) * N + xx0]     : z;
        float2 p11 = (v1 && u1) ? pr[(yy0 + 1) * N + xx0 + 1] : z;
        float amp = w00 * p00.x + w01 * p01.x + w10 * p10.x + w11 * p11.x;
        float ph  = w00 * p00.y + w01 * p01.y + w10 * p10.y + w11 * p11.y;
        float s, c; __sincosf(ph, &s, &c);
        float2 pc = make_float2(amp * c, amp * s);
        float2 o  = ob[(py + y) * 1024 + (px + x)];
        float s2, c2; __sincosf(o.y, &s2, &c2);
        float2 oc = make_float2(o.x * c2, o.x * s2);
        sA[warp * LSTR + x] = cmulf(pc, oc);
    }
    __syncthreads();
    fft_lines<false>(sA, sB, sT, t);

    float2* gp = g_psi + tile * (N * N) + y0 * N;
    #pragma unroll
    for (int k = 0; k < 8; k++) {
        const int e = t + k * 256;
        gp[e] = sA[(e >> 8) * LSTR + (e & 255)];
    }
}

// ---------------------------------------------------------------------------
// Column pass: Fc -> *H*(1/256) -> IFc, in place on g_psi. 8 columns per CTA.
__global__ void k_col() {
    __shared__ float2 sA[LINES * LSTR];
    __shared__ float2 sB[LINES * LSTR];
    __shared__ float2 sT[128];
    const int t = threadIdx.x;
    fill_tw(sT, t);

    const int tile = blockIdx.y;
    const int x0 = blockIdx.x * LINES;
    float2* gp = g_psi + tile * (N * N);

    #pragma unroll
    for (int k = 0; k < 8; k++) {
        const int e = t + k * 256;
        sA[(e & 7) * LSTR + (e >> 3)] = gp[(e >> 3) * N + x0 + (e & 7)];
    }
    __syncthreads();
    fft_lines<false>(sA, sB, sT, t);   // natural ky per column line

    const int c = t >> 5, lane = t & 31;
    #pragma unroll
    for (int k = 0; k < 8; k++) {
        const int ky = lane + 32 * k;
        float2 h = g_Ht[(x0 + c) * N + ky];
        h.x *= (1.0f / 256.0f);
        h.y *= (1.0f / 256.0f);
        sA[c * LSTR + ky] = cmulf(sA[c * LSTR + ky], h);
    }
    __syncthreads();
    fft_lines<true>(sA, sB, sT, t);

    #pragma unroll
    for (int k = 0; k < 8; k++) {
        const int e = t + k * 256;
        gp[(e >> 3) * N + x0 + (e & 7)] = sA[(e & 7) * LSTR + (e >> 3)];
    }
}

// ---------------------------------------------------------------------------
// Mid row pass: IFr*(1/256) -> *obj[z] -> Fr, in place on g_psi.
__global__ void k_mid_row(const float* __restrict__ obj,
                          const int*   __restrict__ cpos,
                          const int*   __restrict__ idxs,
                          int z) {
    __shared__ float2 sA[LINES * LSTR];
    __shared__ float2 sB[LINES * LSTR];
    __shared__ float2 sT[128];
    const int t = threadIdx.x;
    fill_tw(sT, t);

    const int tile = blockIdx.y;
    const int b = tile >> 2;
    const int y0 = blockIdx.x * LINES;
    const int idx = idxs[b];
    const int py = cpos[2 * idx], px = cpos[2 * idx + 1];

    float2* gp = g_psi + tile * (N * N) + y0 * N;
    #pragma unroll
    for (int k = 0; k < 8; k++) {
        const int e = t + k * 256;
        sA[(e >> 8) * LSTR + (e & 255)] = gp[e];
    }
    __syncthreads();
    fft_lines<true>(sA, sB, sT, t);   // spatial x, missing 1/256 (folded below)

    const int warp = t >> 5, lane = t & 31;
    const int y = y0 + warp;
    const float2* ob = (const float2*)obj + z * 1024 * 1024;
    #pragma unroll
    for (int k = 0; k < 8; k++) {
        const int x = lane + 32 * k;
        float2 v = sA[warp * LSTR + x];
        float2 o = ob[(py + y) * 1024 + (px + x)];
        float s, c; __sincosf(o.y, &s, &c);
        const float a = o.x * (1.0f / 256.0f);
        sA[warp * LSTR + x] = cmulf(v, make_float2(a * c, a * s));
    }
    __syncthreads();
    fft_lines<false>(sA, sB, sT, t);

    #pragma unroll
    for (int k = 0; k < 8; k++) {
        const int e = t + k * 256;
        gp[e] = sA[(e >> 8) * LSTR + (e & 255)];
    }
}

// ---------------------------------------------------------------------------
// Final: Fc per column, accumulate |.|^2 over 4 probe modes -> out[b][ky][kx]
__global__ void k_final(float* __restrict__ out) {
    __shared__ float2 sA[LINES * LSTR];
    __shared__ float2 sB[LINES * LSTR];
    __shared__ float2 sT[128];
    const int t = threadIdx.x;
    fill_tw(sT, t);

    const int b = blockIdx.y;
    const int x0 = blockIdx.x * LINES;
    float acc[8];
    #pragma unroll
    for (int k = 0; k < 8; k++) acc[k] = 0.f;

    for (int m = 0; m < 4; m++) {
        const int tile = b * 4 + m;
        const float2* gp = g_psi + tile * (N * N);
        __syncthreads();   // protect sA from prior iteration's reads
        #pragma unroll
        for (int k = 0; k < 8; k++) {
            const int e = t + k * 256;
            sA[(e & 7) * LSTR + (e >> 3)] = gp[(e >> 3) * N + x0 + (e & 7)];
        }
        __syncthreads();
        fft_lines<false>(sA, sB, sT, t);
        #pragma unroll
        for (int k = 0; k < 8; k++) {
            const int e = t + k * 256;
            float2 v = sA[(e & 7) * LSTR + (e >> 3)];
            acc[k] += v.x * v.x + v.y * v.y;
        }
    }
    #pragma unroll
    for (int k = 0; k < 8; k++) {
        const int e = t + k * 256;
        out[b * (N * N) + (e >> 3) * N + x0 + (e & 7)] = acc[k];
    }
}

// ---------------------------------------------------------------------------
extern "C" void kernel_launch(void* const* d_in, const int* in_sizes, int n_in,
                              void* d_out, int out_size) {
    const float* obj    = (const float*)d_in[0];
    const float* probe  = (const float*)d_in[1];
    const float* shifts = (const float*)d_in[2];
    const int*   cpos   = (const int*)d_in[3];
    const float* Hr     = (const float*)d_in[4];
    const float* Hi     = (const float*)d_in[5];
    const int*   idxs   = (const int*)d_in[6];
    float* out = (float*)d_out;

    k_transpose<<<256, 256>>>(Hr, Hi);

    dim3 g(32, NTILE);   // 32 line-chunks x 128 tiles
    k_init_row<<<g, 256>>>(obj, probe, shifts, cpos, idxs);
    for (int z = 0; z < 7; z++) {
        k_col<<<g, 256>>>();
        k_mid_row<<<g, 256>>>(obj, cpos, idxs, z + 1);
    }
    dim3 gf(32, BATCH);
    k_final<<<gf, 256>>>(out);
}

// round 2
// speedup vs baseline: 1.9973x; 1.9973x over previous
#include <cuda_runtime.h>
#include <math.h>

#define N 256
#define NTILE 128
#define BATCH 32

// 64 MB scratch: psi, rows y-major; x dimension stored in permuted spectral order
__device__ float2 g_psi[NTILE * N * N];
// permuted + prescaled transfer function: g_Hp[sx*256 + k2*32 + l] = H[k2+8*br5(l)][kx(sx)]/256
__device__ float2 g_Hp[N * N];

__device__ __forceinline__ float2 cmul(float2 a, float2 b) {
    return make_float2(fmaf(a.x, b.x, -a.y * b.y), fmaf(a.x, b.y, a.y * b.x));
}
__device__ __forceinline__ float2 cadd(float2 a, float2 b){ return make_float2(a.x+b.x, a.y+b.y); }
__device__ __forceinline__ float2 csub(float2 a, float2 b){ return make_float2(a.x-b.x, a.y-b.y); }
__device__ __forceinline__ float2 cconj(float2 a){ return make_float2(a.x, -a.y); }
__device__ __forceinline__ int br5(int x){ return (int)(__brev((unsigned)x) >> 27); }

// ---------------------------------------------------------------------------
// Per-thread twiddle context (computed once per kernel)
struct Tw {
    float2 Wf[5];   // forward lane-DIF stage twiddles (h=16,8,4,2,1); identity on clear lanes
    float2 Wi[5];   // inverse lane-DIT stage twiddles (h=1,2,4,8,16); sign+conj folded
    float2 wp[7];   // W_256^{l*k}, k=1..7
};

__device__ __forceinline__ void tw_init(Tw& T, int l) {
    #pragma unroll
    for (int s = 0; s < 5; s++) {
        const int h = 16 >> s;
        const int idx = l & (h - 1);
        float sn, cs;
        sincospif((float)idx / (float)h, &sn, &cs);   // W = (cs, -sn) = e^{-i pi idx/h}
        T.Wf[s] = (l & h) ? make_float2(cs, -sn) : make_float2(1.f, 0.f);
    }
    #pragma unroll
    for (int s = 0; s < 5; s++) {
        const int h = 1 << s;
        const int idx = l & (h - 1);
        float sn, cs;
        sincospif((float)idx / (float)h, &sn, &cs);
        // conj(W) = (cs, sn); bit-set lanes use -conj(W)
        T.Wi[s] = (l & h) ? make_float2(-cs, -sn) : make_float2(cs, sn);
    }
    float sn, cs;
    sincospif((float)l / 128.f, &sn, &cs);
    float2 w1 = make_float2(cs, -sn);                 // W_256^l
    T.wp[0] = w1;
    float2 w2 = cmul(w1, w1);
    T.wp[1] = w2;
    T.wp[2] = cmul(w2, w1);
    float2 w4 = cmul(w2, w2);
    T.wp[3] = w4;
    T.wp[4] = cmul(w4, w1);
    T.wp[5] = cmul(w4, w2);
    T.wp[6] = cmul(T.wp[5], w1);
}

// ---------------------------------------------------------------------------
// 8-point FFT in registers, natural in / natural out (DIT with reg bit-reversal)
template<bool INV>
__device__ __forceinline__ void fft8(float2 v[8]) {
    float2 a0=v[0], a1=v[4], a2=v[2], a3=v[6], a4=v[1], a5=v[5], a6=v[3], a7=v[7];
    float2 b0=cadd(a0,a1), b1=csub(a0,a1);
    float2 b2=cadd(a2,a3), b3=csub(a2,a3);
    float2 b4=cadd(a4,a5), b5=csub(a4,a5);
    float2 b6=cadd(a6,a7), b7=csub(a6,a7);
    float2 b3t = INV ? make_float2(-b3.y, b3.x) : make_float2(b3.y, -b3.x);  // *(+/-i)
    float2 b7t = INV ? make_float2(-b7.y, b7.x) : make_float2(b7.y, -b7.x);
    float2 c0=cadd(b0,b2), c2=csub(b0,b2);
    float2 c1=cadd(b1,b3t), c3=csub(b1,b3t);
    float2 c4=cadd(b4,b6), c6=csub(b4,b6);
    float2 c5=cadd(b5,b7t), c7=csub(b5,b7t);
    const float r = 0.70710678118654752440f;
    float2 w1 = INV ? make_float2(r,  r) : make_float2( r, -r);
    float2 w3 = INV ? make_float2(-r, r) : make_float2(-r, -r);
    float2 c5t = cmul(c5, w1);
    float2 c6t = INV ? make_float2(-c6.y, c6.x) : make_float2(c6.y, -c6.x);
    float2 c7t = cmul(c7, w3);
    v[0]=cadd(c0,c4); v[4]=csub(c0,c4);
    v[1]=cadd(c1,c5t); v[5]=csub(c1,c5t);
    v[2]=cadd(c2,c6t); v[6]=csub(c2,c6t);
    v[3]=cadd(c3,c7t); v[7]=csub(c3,c7t);
}

// 32-point FFT across warp lanes: forward DIF (natural in -> bit-reversed lanes out)
__device__ __forceinline__ void lane_fwd(float2 v[8], const Tw& T, int l) {
    #pragma unroll
    for (int s = 0; s < 5; s++) {
        const int h = 16 >> s;
        const float sgn = (l & h) ? -1.f : 1.f;
        #pragma unroll
        for (int k = 0; k < 8; k++) {
            float px = __shfl_xor_sync(0xffffffffu, v[k].x, h);
            float py = __shfl_xor_sync(0xffffffffu, v[k].y, h);
            float2 u = make_float2(fmaf(sgn, v[k].x, px), fmaf(sgn, v[k].y, py));
            v[k] = cmul(u, T.Wf[s]);
        }
    }
}
// inverse DIT (bit-reversed lanes in -> natural out), conjugate twiddles, unnormalized
__device__ __forceinline__ void lane_inv(float2 v[8], const Tw& T, int l) {
    #pragma unroll
    for (int s = 0; s < 5; s++) {
        const int h = 1 << s;
        const bool bit = (l & h) != 0;
        #pragma unroll
        for (int k = 0; k < 8; k++) {
            float px = __shfl_xor_sync(0xffffffffu, v[k].x, h);
            float py = __shfl_xor_sync(0xffffffffu, v[k].y, h);
            float2 p = make_float2(px, py);
            float2 base = bit ? p : v[k];
            float2 oth  = bit ? v[k] : p;
            v[k] = cadd(base, cmul(T.Wi[s], oth));
        }
    }
}

// Full 256-pt line FFT. Input: v[n2] = x[l + 32*n2].
// Output: v[k2] = X[k2 + 8*br5(l)]  (stored at index k2*32+l -> "permuted spectral")
__device__ __forceinline__ void fwd256(float2 v[8], const Tw& T, int l) {
    fft8<false>(v);
    #pragma unroll
    for (int k = 1; k < 8; k++) v[k] = cmul(v[k], T.wp[k-1]);
    lane_fwd(v, T, l);
}
// Exact unnormalized inverse of fwd256 (x256)
__device__ __forceinline__ void inv256(float2 v[8], const Tw& T, int l) {
    lane_inv(v, T, l);
    #pragma unroll
    for (int k = 1; k < 8; k++) v[k] = cmul(v[k], cconj(T.wp[k-1]));
    fft8<true>(v);
}

// ---------------------------------------------------------------------------
// Build permuted, prescaled H table
__global__ void k_prep(const float* __restrict__ Hr, const float* __restrict__ Hi) {
    int o = blockIdx.x * 256 + threadIdx.x;       // 65536 total
    int s = o >> 8, j = o & 255;
    int ky = (j >> 5) + 8 * br5(j & 31);
    int kx = (s >> 5) + 8 * br5(s & 31);
    int src = ky * N + kx;
    g_Hp[o] = make_float2(Hr[src] * (1.f/256.f), Hi[src] * (1.f/256.f));
}

// ---------------------------------------------------------------------------
// Init: psi0 = bilinear(probe) * obj[0], forward row FFT -> g_psi (no smem)
__global__ void __launch_bounds__(256) k_init_row(
        const float* __restrict__ obj, const float* __restrict__ probe,
        const float* __restrict__ shifts, const int* __restrict__ cpos,
        const int* __restrict__ idxs) {
    const int t = threadIdx.x, l = t & 31, w = t >> 5;
    Tw T; tw_init(T, l);

    const int tile = blockIdx.y;
    const int b = tile >> 2, m = tile & 3;
    const int y = blockIdx.x * 8 + w;
    const int idx = idxs[b];
    const int py = cpos[2*idx], px = cpos[2*idx + 1];
    const float tH = shifts[2*idx], tW = shifts[2*idx + 1];
    const float oyf = floorf(-tH), oxf = floorf(-tW);
    const int oy = (int)oyf, ox = (int)oxf;
    const float wy = -tH - oyf, wx = -tW - oxf;
    const float w00 = (1.f-wy)*(1.f-wx), w01 = (1.f-wy)*wx;
    const float w10 = wy*(1.f-wx),       w11 = wy*wx;

    const int yy0 = y + oy;
    const bool v0 = (yy0 >= 0) && (yy0 < N);
    const bool v1 = (yy0 + 1 >= 0) && (yy0 + 1 < N);
    const float2* pr = (const float2*)probe + m * N * N;
    const float2* ob = (const float2*)obj + (py + y) * 1024 + px;   // slice 0

    float2 v[8];
    #pragma unroll
    for (int n2 = 0; n2 < 8; n2++) {
        const int x = l + 32 * n2;
        const int xx0 = x + ox;
        const bool u0 = (xx0 >= 0) && (xx0 < N);
        const bool u1 = (xx0 + 1 >= 0) && (xx0 + 1 < N);
        float2 z = make_float2(0.f, 0.f);
        float2 p00 = (v0 && u0) ? pr[yy0*N + xx0]       : z;
        float2 p01 = (v0 && u1) ? pr[yy0*N + xx0 + 1]   : z;
        float2 p10 = (v1 && u0) ? pr[(yy0+1)*N + xx0]   : z;
        float2 p11 = (v1 && u1) ? pr[(yy0+1)*N + xx0+1] : z;
        float amp = w00*p00.x + w01*p01.x + w10*p10.x + w11*p11.x;
        float ph  = w00*p00.y + w01*p01.y + w10*p10.y + w11*p11.y;
        float s, c; __sincosf(ph, &s, &c);
        float2 pc = make_float2(amp * c, amp * s);
        float2 o = ob[x];
        float s2, c2; __sincosf(o.y, &s2, &c2);
        v[n2] = cmul(pc, make_float2(o.x * c2, o.x * s2));
    }
    fwd256(v, T, l);
    float2* gp = g_psi + tile * N * N + y * N;
    #pragma unroll
    for (int k2 = 0; k2 < 8; k2++) gp[k2*32 + l] = v[k2];
}

// ---------------------------------------------------------------------------
// Column pass: Fy -> *H/256 -> IFy per storage-column. smem only for staging.
__global__ void __launch_bounds__(256) k_col() {
    __shared__ float2 sm[8 * 257];
    const int t = threadIdx.x, l = t & 31, w = t >> 5;
    Tw T; tw_init(T, l);

    const int tile = blockIdx.y;
    const int sx0 = blockIdx.x * 8;
    float2* gp = g_psi + tile * N * N;

    #pragma unroll
    for (int k = 0; k < 8; k++) {
        const int e = t + k * 256;
        const int y = e >> 3, c = e & 7;
        sm[c * 257 + y] = gp[y * N + sx0 + c];
    }
    __syncthreads();

    float2 v[8];
    #pragma unroll
    for (int n2 = 0; n2 < 8; n2++) v[n2] = sm[w * 257 + l + 32 * n2];
    fwd256(v, T, l);
    const float2* hp = g_Hp + (sx0 + w) * N;
    #pragma unroll
    for (int k2 = 0; k2 < 8; k2++) v[k2] = cmul(v[k2], hp[k2*32 + l]);
    inv256(v, T, l);
    #pragma unroll
    for (int n2 = 0; n2 < 8; n2++) sm[w * 257 + l + 32 * n2] = v[n2];
    __syncthreads();

    #pragma unroll
    for (int k = 0; k < 8; k++) {
        const int e = t + k * 256;
        const int y = e >> 3, c = e & 7;
        gp[y * N + sx0 + c] = sm[c * 257 + y];
    }
}

// ---------------------------------------------------------------------------
// Mid row pass: IFx -> *obj[z]/256 -> Fx. Fully register/shuffle, no smem.
__global__ void __launch_bounds__(256) k_mid_row(
        const float* __restrict__ obj, const int* __restrict__ cpos,
        const int* __restrict__ idxs, int z) {
    const int t = threadIdx.x, l = t & 31, w = t >> 5;
    Tw T; tw_init(T, l);

    const int tile = blockIdx.y, b = tile >> 2;
    const int y = blockIdx.x * 8 + w;
    const int idx = idxs[b];
    const int py = cpos[2*idx], px = cpos[2*idx + 1];

    float2* gp = g_psi + tile * N * N + y * N;
    float2 v[8];
    #pragma unroll
    for (int k2 = 0; k2 < 8; k2++) v[k2] = gp[k2*32 + l];
    inv256(v, T, l);

    const float2* ob = (const float2*)obj + (size_t)z * 1024 * 1024 + (py + y) * 1024 + px;
    #pragma unroll
    for (int n2 = 0; n2 < 8; n2++) {
        float2 o = ob[l + 32 * n2];
        float s, c; __sincosf(o.y, &s, &c);
        const float a = o.x * (1.f / 256.f);
        v[n2] = cmul(v[n2], make_float2(a * c, a * s));
    }
    fwd256(v, T, l);
    #pragma unroll
    for (int k2 = 0; k2 < 8; k2++) gp[k2*32 + l] = v[k2];
}

// ---------------------------------------------------------------------------
// Final: Fy per column, sum |.|^2 over 4 modes, scatter to true (ky,kx)
__global__ void __launch_bounds__(256) k_final(float* __restrict__ out) {
    __shared__ float2 sm[8 * 257];
    const int t = threadIdx.x, l = t & 31, w = t >> 5;
    Tw T; tw_init(T, l);

    const int b = blockIdx.y;
    const int sx0 = blockIdx.x * 8;
    float acc[8];
    #pragma unroll
    for (int k = 0; k < 8; k++) acc[k] = 0.f;

    for (int m = 0; m < 4; m++) {
        const float2* gp = g_psi + (size_t)(b * 4 + m) * N * N;
        __syncthreads();
        #pragma unroll
        for (int k = 0; k < 8; k++) {
            const int e = t + k * 256;
            sm[(e & 7) * 257 + (e >> 3)] = gp[(e >> 3) * N + sx0 + (e & 7)];
        }
        __syncthreads();
        float2 v[8];
        #pragma unroll
        for (int n2 = 0; n2 < 8; n2++) v[n2] = sm[w * 257 + l + 32 * n2];
        fwd256(v, T, l);
        #pragma unroll
        for (int k2 = 0; k2 < 8; k2++)
            acc[k2] += v[k2].x * v[k2].x + v[k2].y * v[k2].y;
    }
    const int s = sx0 + w;
    const int kx = (s >> 5) + 8 * br5(s & 31);
    const int kyb = 8 * br5(l);
    #pragma unroll
    for (int k2 = 0; k2 < 8; k2++)
        out[b * N * N + (k2 + kyb) * N + kx] = acc[k2];
}

// ---------------------------------------------------------------------------
extern "C" void kernel_launch(void* const* d_in, const int* in_sizes, int n_in,
                              void* d_out, int out_size) {
    const float* obj    = (const float*)d_in[0];
    const float* probe  = (const float*)d_in[1];
    const float* shifts = (const float*)d_in[2];
    const int*   cpos   = (const int*)d_in[3];
    const float* Hr     = (const float*)d_in[4];
    const float* Hi     = (const float*)d_in[5];
    const int*   idxs   = (const int*)d_in[6];
    float* out = (float*)d_out;

    k_prep<<<256, 256>>>(Hr, Hi);

    dim3 g(32, NTILE);
    k_init_row<<<g, 256>>>(obj, probe, shifts, cpos, idxs);
    for (int z = 0; z < 7; z++) {
        k_col<<<g, 256>>>();
        k_mid_row<<<g, 256>>>(obj, cpos, idxs, z + 1);
    }
    dim3 gf(32, BATCH);
    k_final<<<gf, 256>>>(out);
}

// round 3
// speedup vs baseline: 2.2121x; 1.1076x over previous
#include <cuda_runtime.h>
#include <math.h>

#define N 256
#define NTILE 128
#define BATCH 32

// 64 MB scratch: psi, rows y-major; x dimension stored in permuted spectral order
__device__ float2 g_psi[NTILE * N * N];
// permuted + prescaled transfer function: g_Hp[sx*256 + k2*32 + l] = H[k2+8*br5(l)][kx(sx)]/256
__device__ float2 g_Hp[N * N];
// per-lane twiddle table, SoA: comp c at g_twt[c*32 + l]
//   c 0..4   : Wf[s]  forward DIF stage twiddle (identity on bit-clear lanes)
//   c 5..9   : A[s]   inverse stage coeff on own value
//   c 10..14 : B[s]   inverse stage coeff on partner value
//   c 15..21 : wp[k]  W_256^{l*(k+1)}
__device__ float2 g_twt[22 * 32];

__device__ __forceinline__ float2 cmul(float2 a, float2 b) {
    return make_float2(fmaf(a.x, b.x, -a.y * b.y), fmaf(a.x, b.y, a.y * b.x));
}
// a * conj(b)
__device__ __forceinline__ float2 cmulc(float2 a, float2 b) {
    return make_float2(fmaf(a.x, b.x, a.y * b.y), fmaf(a.y, b.x, -a.x * b.y));
}
// A*v + B*p (complex)
__device__ __forceinline__ float2 cmul2(float2 A, float2 v, float2 B, float2 p) {
    float rx = fmaf(A.x, v.x, fmaf(-A.y, v.y, fmaf(B.x, p.x, -B.y * p.y)));
    float ry = fmaf(A.x, v.y, fmaf( A.y, v.x, fmaf(B.x, p.y,  B.y * p.x)));
    return make_float2(rx, ry);
}
__device__ __forceinline__ int br5(int x){ return (int)(__brev((unsigned)x) >> 27); }

// ---- packed f32x2 helpers (sm_100+) --------------------------------------
__device__ __forceinline__ float2 padd(float2 a, float2 b) {
    float2 r;
    asm("{\n\t.reg .b64 ua, ub, ur;\n\t"
        "mov.b64 ua, {%2,%3};\n\t"
        "mov.b64 ub, {%4,%5};\n\t"
        "add.rn.f32x2 ur, ua, ub;\n\t"
        "mov.b64 {%0,%1}, ur;\n\t}"
        : "=f"(r.x), "=f"(r.y)
        : "f"(a.x), "f"(a.y), "f"(b.x), "f"(b.y));
    return r;
}
// a*b + c, packed per component
__device__ __forceinline__ float2 pfma(float2 a, float2 b, float2 c) {
    float2 r;
    asm("{\n\t.reg .b64 ua, ub, uc, ur;\n\t"
        "mov.b64 ua, {%2,%3};\n\t"
        "mov.b64 ub, {%4,%5};\n\t"
        "mov.b64 uc, {%6,%7};\n\t"
        "fma.rn.f32x2 ur, ua, ub, uc;\n\t"
        "mov.b64 {%0,%1}, ur;\n\t}"
        : "=f"(r.x), "=f"(r.y)
        : "f"(a.x), "f"(a.y), "f"(b.x), "f"(b.y), "f"(c.x), "f"(c.y));
    return r;
}
__device__ __forceinline__ float2 psub(float2 a, float2 b) {
    return pfma(b, make_float2(-1.f, -1.f), a);   // a - b (exact)
}

// ---------------------------------------------------------------------------
// 8-point FFT in registers, natural in / natural out
template<bool INV>
__device__ __forceinline__ void fft8(float2 v[8]) {
    float2 a0=v[0], a1=v[4], a2=v[2], a3=v[6], a4=v[1], a5=v[5], a6=v[3], a7=v[7];
    float2 b0=padd(a0,a1), b1=psub(a0,a1);
    float2 b2=padd(a2,a3), b3=psub(a2,a3);
    float2 b4=padd(a4,a5), b5=psub(a4,a5);
    float2 b6=padd(a6,a7), b7=psub(a6,a7);
    float2 b3t = INV ? make_float2(-b3.y, b3.x) : make_float2(b3.y, -b3.x);
    float2 b7t = INV ? make_float2(-b7.y, b7.x) : make_float2(b7.y, -b7.x);
    float2 c0=padd(b0,b2), c2=psub(b0,b2);
    float2 c1=padd(b1,b3t), c3=psub(b1,b3t);
    float2 c4=padd(b4,b6), c6=psub(b4,b6);
    float2 c5=padd(b5,b7t), c7=psub(b5,b7t);
    const float r = 0.70710678118654752440f;
    float2 w1 = INV ? make_float2(r,  r) : make_float2( r, -r);
    float2 w3 = INV ? make_float2(-r, r) : make_float2(-r, -r);
    float2 c5t = cmul(c5, w1);
    float2 c6t = INV ? make_float2(-c6.y, c6.x) : make_float2(c6.y, -c6.x);
    float2 c7t = cmul(c7, w3);
    v[0]=padd(c0,c4); v[4]=psub(c0,c4);
    v[1]=padd(c1,c5t); v[5]=psub(c1,c5t);
    v[2]=padd(c2,c6t); v[6]=psub(c2,c6t);
    v[3]=padd(c3,c7t); v[7]=psub(c3,c7t);
}

// 32-pt FFT across lanes, forward DIF: natural in -> bit-reversed lanes out
__device__ __forceinline__ void lane_fwd(float2 v[8], const float2* tt, int l) {
    #pragma unroll
    for (int s = 0; s < 5; s++) {
        const int h = 16 >> s;
        const float sgn = (l & h) ? -1.f : 1.f;
        const float2 sgnP = make_float2(sgn, sgn);
        const float2 W = tt[s * 32];
        #pragma unroll
        for (int k = 0; k < 8; k++) {
            float px = __shfl_xor_sync(0xffffffffu, v[k].x, h);
            float py = __shfl_xor_sync(0xffffffffu, v[k].y, h);
            float2 u = pfma(v[k], sgnP, make_float2(px, py));
            v[k] = cmul(u, W);
        }
    }
}
// inverse DIT: bit-reversed lanes in -> natural out; out = A*v + B*p
__device__ __forceinline__ void lane_inv(float2 v[8], const float2* tt, int l) {
    #pragma unroll
    for (int s = 0; s < 5; s++) {
        const int h = 1 << s;
        const float2 A = tt[(5 + s) * 32];
        const float2 B = tt[(10 + s) * 32];
        #pragma unroll
        for (int k = 0; k < 8; k++) {
            float px = __shfl_xor_sync(0xffffffffu, v[k].x, h);
            float py = __shfl_xor_sync(0xffffffffu, v[k].y, h);
            v[k] = cmul2(A, v[k], B, make_float2(px, py));
        }
    }
}

// Full 256-pt line FFT. Input v[n2] = x[l + 32*n2];
// output v[k2] = X[k2 + 8*br5(l)] (stored at k2*32+l -> permuted spectral)
__device__ __forceinline__ void fwd256(float2 v[8], const float2* tt, int l) {
    fft8<false>(v);
    #pragma unroll
    for (int k = 1; k < 8; k++) v[k] = cmul(v[k], tt[(15 + k - 1) * 32]);
    lane_fwd(v, tt, l);
}
// exact unnormalized inverse of fwd256 (x256)
__device__ __forceinline__ void inv256(float2 v[8], const float2* tt, int l) {
    lane_inv(v, tt, l);
    #pragma unroll
    for (int k = 1; k < 8; k++) v[k] = cmulc(v[k], tt[(15 + k - 1) * 32]);
    fft8<true>(v);
}

// ---------------------------------------------------------------------------
// Build permuted/prescaled H table and the per-lane twiddle table
__global__ void k_prep(const float* __restrict__ Hr, const float* __restrict__ Hi) {
    int o = blockIdx.x * 256 + threadIdx.x;       // 65536 total
    int s = o >> 8, j = o & 255;
    int ky = (j >> 5) + 8 * br5(j & 31);
    int kx = (s >> 5) + 8 * br5(s & 31);
    int src = ky * N + kx;
    g_Hp[o] = make_float2(Hr[src] * (1.f/256.f), Hi[src] * (1.f/256.f));

    if (o < 32) {
        const int l = o;
        // forward stage twiddles (h = 16 >> s)
        for (int st = 0; st < 5; st++) {
            const int h = 16 >> st;
            const int idx = l & (h - 1);
            float sn, cs;
            sincospif((float)idx / (float)h, &sn, &cs);   // W = (cs,-sn)
            g_twt[st * 32 + l] = (l & h) ? make_float2(cs, -sn) : make_float2(1.f, 0.f);
        }
        // inverse stage coeffs (h = 1 << s): conjW = (cs, sn)
        for (int st = 0; st < 5; st++) {
            const int h = 1 << st;
            const int idx = l & (h - 1);
            float sn, cs;
            sincospif((float)idx / (float)h, &sn, &cs);
            float2 A = (l & h) ? make_float2(-cs, -sn) : make_float2(1.f, 0.f);
            float2 B = (l & h) ? make_float2(1.f, 0.f) : make_float2(cs, sn);
            g_twt[(5 + st) * 32 + l]  = A;
            g_twt[(10 + st) * 32 + l] = B;
        }
        // W_256^{l*k}, k=1..7
        float sn, cs;
        sincospif((float)l / 128.f, &sn, &cs);
        float2 w1 = make_float2(cs, -sn);
        float2 wk = w1;
        g_twt[15 * 32 + l] = wk;
        for (int k = 2; k <= 7; k++) {
            wk = cmul(wk, w1);
            g_twt[(15 + k - 1) * 32 + l] = wk;
        }
    }
}

// ---------------------------------------------------------------------------
// Init: psi0 = bilinear(probe) * obj[0], forward row FFT -> g_psi (no smem)
__global__ void __launch_bounds__(256) k_init_row(
        const float* __restrict__ obj, const float* __restrict__ probe,
        const float* __restrict__ shifts, const int* __restrict__ cpos,
        const int* __restrict__ idxs) {
    const int t = threadIdx.x, l = t & 31, w = t >> 5;
    const float2* tt = g_twt + l;

    const int tile = blockIdx.y;
    const int b = tile >> 2, m = tile & 3;
    const int y = blockIdx.x * 8 + w;
    const int idx = idxs[b];
    const int py = cpos[2*idx], px = cpos[2*idx + 1];
    const float tH = shifts[2*idx], tW = shifts[2*idx + 1];
    const float oyf = floorf(-tH), oxf = floorf(-tW);
    const int oy = (int)oyf, ox = (int)oxf;
    const float wy = -tH - oyf, wx = -tW - oxf;
    const float w00 = (1.f-wy)*(1.f-wx), w01 = (1.f-wy)*wx;
    const float w10 = wy*(1.f-wx),       w11 = wy*wx;

    const int yy0 = y + oy;
    const bool v0 = (yy0 >= 0) && (yy0 < N);
    const bool v1 = (yy0 + 1 >= 0) && (yy0 + 1 < N);
    const float2* pr = (const float2*)probe + m * N * N;
    const float2* ob = (const float2*)obj + (py + y) * 1024 + px;   // slice 0

    float2 v[8];
    #pragma unroll
    for (int n2 = 0; n2 < 8; n2++) {
        const int x = l + 32 * n2;
        const int xx0 = x + ox;
        const bool u0 = (xx0 >= 0) && (xx0 < N);
        const bool u1 = (xx0 + 1 >= 0) && (xx0 + 1 < N);
        float2 z = make_float2(0.f, 0.f);
        float2 p00 = (v0 && u0) ? pr[yy0*N + xx0]       : z;
        float2 p01 = (v0 && u1) ? pr[yy0*N + xx0 + 1]   : z;
        float2 p10 = (v1 && u0) ? pr[(yy0+1)*N + xx0]   : z;
        float2 p11 = (v1 && u1) ? pr[(yy0+1)*N + xx0+1] : z;
        float amp = w00*p00.x + w01*p01.x + w10*p10.x + w11*p11.x;
        float ph  = w00*p00.y + w01*p01.y + w10*p10.y + w11*p11.y;
        float s, c; __sincosf(ph, &s, &c);
        float2 pc = make_float2(amp * c, amp * s);
        float2 o = ob[x];
        float s2, c2; __sincosf(o.y, &s2, &c2);
        v[n2] = cmul(pc, make_float2(o.x * c2, o.x * s2));
    }
    fwd256(v, tt, l);
    float2* gp = g_psi + tile * N * N + y * N;
    #pragma unroll
    for (int k2 = 0; k2 < 8; k2++) gp[k2*32 + l] = v[k2];
}

// ---------------------------------------------------------------------------
// Column pass: Fy -> *H/256 -> IFy per storage-column. smem only for staging.
__global__ void __launch_bounds__(256) k_col() {
    __shared__ float2 sm[8 * 257];
    const int t = threadIdx.x, l = t & 31, w = t >> 5;
    const float2* tt = g_twt + l;

    const int tile = blockIdx.y;
    const int sx0 = blockIdx.x * 8;
    float2* gp = g_psi + tile * N * N;

    #pragma unroll
    for (int k = 0; k < 8; k++) {
        const int e = t + k * 256;
        const int y = e >> 3, c = e & 7;
        sm[c * 257 + y] = gp[y * N + sx0 + c];
    }
    __syncthreads();

    float2 v[8];
    #pragma unroll
    for (int n2 = 0; n2 < 8; n2++) v[n2] = sm[w * 257 + l + 32 * n2];
    fwd256(v, tt, l);
    const float2* hp = g_Hp + (sx0 + w) * N;
    #pragma unroll
    for (int k2 = 0; k2 < 8; k2++) v[k2] = cmul(v[k2], hp[k2*32 + l]);
    inv256(v, tt, l);
    #pragma unroll
    for (int n2 = 0; n2 < 8; n2++) sm[w * 257 + l + 32 * n2] = v[n2];
    __syncthreads();

    #pragma unroll
    for (int k = 0; k < 8; k++) {
        const int e = t + k * 256;
        const int y = e >> 3, c = e & 7;
        gp[y * N + sx0 + c] = sm[c * 257 + y];
    }
}

// ---------------------------------------------------------------------------
// Mid row pass: IFx -> *obj[z]/256 -> Fx. Fully register/shuffle, no smem.
__global__ void __launch_bounds__(256) k_mid_row(
        const float* __restrict__ obj, const int* __restrict__ cpos,
        const int* __restrict__ idxs, int z) {
    const int t = threadIdx.x, l = t & 31, w = t >> 5;
    const float2* tt = g_twt + l;

    const int tile = blockIdx.y, b = tile >> 2;
    const int y = blockIdx.x * 8 + w;
    const int idx = idxs[b];
    const int py = cpos[2*idx], px = cpos[2*idx + 1];

    float2* gp = g_psi + tile * N * N + y * N;
    float2 v[8];
    #pragma unroll
    for (int k2 = 0; k2 < 8; k2++) v[k2] = gp[k2*32 + l];
    inv256(v, tt, l);

    const float2* ob = (const float2*)obj + (size_t)z * 1024 * 1024 + (py + y) * 1024 + px;
    #pragma unroll
    for (int n2 = 0; n2 < 8; n2++) {
        float2 o = ob[l + 32 * n2];
        float s, c; __sincosf(o.y, &s, &c);
        const float a = o.x * (1.f / 256.f);
        v[n2] = cmul(v[n2], make_float2(a * c, a * s));
    }
    fwd256(v, tt, l);
    #pragma unroll
    for (int k2 = 0; k2 < 8; k2++) gp[k2*32 + l] = v[k2];
}

// ---------------------------------------------------------------------------
// Final: Fy per column, sum |.|^2 over 4 modes, scatter to true (ky,kx)
__global__ void __launch_bounds__(256) k_final(float* __restrict__ out) {
    __shared__ float2 sm[8 * 257];
    const int t = threadIdx.x, l = t & 31, w = t >> 5;
    const float2* tt = g_twt + l;

    const int b = blockIdx.y;
    const int sx0 = blockIdx.x * 8;
    float acc[8];
    #pragma unroll
    for (int k = 0; k < 8; k++) acc[k] = 0.f;

    for (int m = 0; m < 4; m++) {
        const float2* gp = g_psi + (size_t)(b * 4 + m) * N * N;
        __syncthreads();
        #pragma unroll
        for (int k = 0; k < 8; k++) {
            const int e = t + k * 256;
            sm[(e & 7) * 257 + (e >> 3)] = gp[(e >> 3) * N + sx0 + (e & 7)];
        }
        __syncthreads();
        float2 v[8];
        #pragma unroll
        for (int n2 = 0; n2 < 8; n2++) v[n2] = sm[w * 257 + l + 32 * n2];
        fwd256(v, tt, l);
        #pragma unroll
        for (int k2 = 0; k2 < 8; k2++)
            acc[k2] = fmaf(v[k2].x, v[k2].x, fmaf(v[k2].y, v[k2].y, acc[k2]));
    }
    const int s = sx0 + w;
    const int kx = (s >> 5) + 8 * br5(s & 31);
    const int kyb = 8 * br5(l);
    #pragma unroll
    for (int k2 = 0; k2 < 8; k2++)
        out[b * N * N + (k2 + kyb) * N + kx] = acc[k2];
}

// ---------------------------------------------------------------------------
extern "C" void kernel_launch(void* const* d_in, const int* in_sizes, int n_in,
                              void* d_out, int out_size) {
    const float* obj    = (const float*)d_in[0];
    const float* probe  = (const float*)d_in[1];
    const float* shifts = (const float*)d_in[2];
    const int*   cpos   = (const int*)d_in[3];
    const float* Hr     = (const float*)d_in[4];
    const float* Hi     = (const float*)d_in[5];
    const int*   idxs   = (const int*)d_in[6];
    float* out = (float*)d_out;

    k_prep<<<256, 256>>>(Hr, Hi);

    dim3 g(32, NTILE);
    k_init_row<<<g, 256>>>(obj, probe, shifts, cpos, idxs);
    for (int z = 0; z < 7; z++) {
        k_col<<<g, 256>>>();
        k_mid_row<<<g, 256>>>(obj, cpos, idxs, z + 1);
    }
    dim3 gf(32, BATCH);
    k_final<<<gf, 256>>>(out);
}